// round 6
// baseline (speedup 1.0000x reference)
#include <cuda_runtime.h>
#include <math.h>
#include <stdint.h>

#define Bn 8
#define C 128
#define HW 16384
#define Ncls 16
#define EPSF 1e-7f
#define NQ 39
#define KS 16
#define KPC (HW/KS)   // 1024 pixels per gram CTA
#define GCHUNK 64

// ---------------- tf32 mma.sync helpers (baseline PTX, sm_80+) ----------------
__device__ __forceinline__ uint32_t f2tf32(float v) {
    uint32_t r; asm("cvt.rna.tf32.f32 %0, %1;" : "=r"(r) : "f"(v)); return r;
}
#define MMA_TF32(d, a0,a1,a2,a3, b0,b1) \
    asm volatile("mma.sync.aligned.m16n8k8.row.col.f32.tf32.tf32.f32 " \
        "{%0,%1,%2,%3}, {%4,%5,%6,%7}, {%8,%9}, {%0,%1,%2,%3};" \
        : "+f"((d)[0]), "+f"((d)[1]), "+f"((d)[2]), "+f"((d)[3]) \
        : "r"(a0), "r"(a1), "r"(a2), "r"(a3), "r"(b0), "r"(b1))

// ---------------- scratch ----------------
__device__ float g_G[Bn*C*C];
__device__ float g_sx[Bn*C];
__device__ float g_H[Bn*3*C*C];
__device__ float g_M[Bn*C*C];    // sigma*diag(A)*Wo (NO identity)
__device__ float g_d[Bn*C];
__device__ float g_red[Bn*NQ*C];
__device__ float g_u[C];

// ---------------- zero scratch + compute u ----------------
__global__ void zero_kernel(const float* __restrict__ Wsa) {
    int i = blockIdx.x * blockDim.x + threadIdx.x;
    if (i < Bn*C*C)  g_G[i] = 0.f;
    if (i < Bn*C)    g_sx[i] = 0.f;
    if (i < Bn*NQ*C) g_red[i] = 0.f;
    if (blockIdx.x == 0 && threadIdx.x < C) {
        float u = 0.f;
        #pragma unroll 4
        for (int r = 0; r < C; r++) u += Wsa[r*C + threadIdx.x];
        g_u[threadIdx.x] = u;
    }
}

// ---------------- Gram via mma.sync tf32: G[b] += X X^T (pipelined) ----------------
// grid (KS, Bn), block 256 (8 warps). Warp w: m-strip [w*16, w*16+16), all 128 n.
__global__ __launch_bounds__(256) void gram_mma_kernel(const float* __restrict__ x) {
    const int ks = blockIdx.x;
    const int b  = blockIdx.y;
    const int tid = threadIdx.x;
    const int w = tid >> 5, lane = tid & 31;
    const int gid = lane >> 2, tig = lane & 3;

    __shared__ uint32_t xt[C*68];   // [c][k] pitch 68, k=64

    float acc[16][4];
    #pragma unroll
    for (int t = 0; t < 16; t++) { acc[t][0]=0.f; acc[t][1]=0.f; acc[t][2]=0.f; acc[t][3]=0.f; }

    const int c   = tid >> 1;
    const int seg = tid & 1;                // 32 pixels each
    const float* xp = x + ((size_t)b*C + c)*HW + ks*KPC + seg*32;
    float ssum = 0.f;

    float4 v[8];
    #pragma unroll
    for (int j = 0; j < 8; j++) v[j] = *reinterpret_cast<const float4*>(xp + j*4);

    for (int it = 0; it < KPC/GCHUNK; it++) {   // 16 iterations of 64 pixels
        // exact fp32 channel sums (pre-conversion)
        #pragma unroll
        for (int j = 0; j < 8; j++) ssum += (v[j].x + v[j].y) + (v[j].z + v[j].w);
        __syncthreads();
        #pragma unroll
        for (int j = 0; j < 8; j++) {
            uint4 u;
            u.x = f2tf32(v[j].x); u.y = f2tf32(v[j].y);
            u.z = f2tf32(v[j].z); u.w = f2tf32(v[j].w);
            *reinterpret_cast<uint4*>(&xt[c*68 + seg*32 + j*4]) = u;
        }
        __syncthreads();
        // prefetch next chunk while MMAs run
        if (it + 1 < KPC/GCHUNK) {
            const float* np = xp + (size_t)(it + 1)*GCHUNK;
            #pragma unroll
            for (int j = 0; j < 8; j++) v[j] = *reinterpret_cast<const float4*>(np + j*4);
        }
        #pragma unroll
        for (int k8 = 0; k8 < 8; k8++) {
            const int kc = k8*8 + tig;
            uint32_t a0 = xt[(w*16 + gid    )*68 + kc];
            uint32_t a1 = xt[(w*16 + gid + 8)*68 + kc];
            uint32_t a2 = xt[(w*16 + gid    )*68 + kc + 4];
            uint32_t a3 = xt[(w*16 + gid + 8)*68 + kc + 4];
            #pragma unroll
            for (int t = 0; t < 16; t++) {
                uint32_t b0 = xt[(t*8 + gid)*68 + kc];
                uint32_t b1 = xt[(t*8 + gid)*68 + kc + 4];
                MMA_TF32(acc[t], a0, a1, a2, a3, b0, b1);
            }
        }
    }

    float* Gb = g_G + b*C*C;
    const int row0 = w*16 + gid;
    #pragma unroll
    for (int t = 0; t < 16; t++) {
        int col0 = t*8 + 2*tig;
        atomicAdd(&Gb[ row0   *C + col0    ], acc[t][0]);
        atomicAdd(&Gb[ row0   *C + col0 + 1], acc[t][1]);
        atomicAdd(&Gb[(row0+8)*C + col0    ], acc[t][2]);
        atomicAdd(&Gb[(row0+8)*C + col0 + 1], acc[t][3]);
    }
    atomicAdd(&g_sx[b*C + c], ssum);
}

// ---------------- H_m[b] = G[b] @ W_m^T ----------------
__global__ __launch_bounds__(256) void hgemm_kernel(const float* __restrict__ Wr,
                                                    const float* __restrict__ Wsa,
                                                    const float* __restrict__ Wo) {
    const int m = blockIdx.x;
    const int b = blockIdx.y;
    const float* W = (m == 0) ? Wr : (m == 1) ? Wsa : Wo;
    const float* G = g_G + b * C * C;
    float* H = g_H + (b * 3 + m) * C * C;

    __shared__ float As[C][33];
    __shared__ float Bs[C][33];
    const int tid = threadIdx.x;
    const int tx = tid & 15, ty = tid >> 4;
    const int kk = tid & 31, r0w = tid >> 5;

    float accA[4][4] = {}, accB[4][4] = {}, accC[4][4] = {}, accD[4][4] = {};

    for (int k0 = 0; k0 < C; k0 += 32) {
        #pragma unroll
        for (int i = 0; i < 16; i++) {
            int r = r0w + i * 8;
            As[r][kk] = G[r*C + k0 + kk];
            Bs[r][kk] = W[r*C + k0 + kk];
        }
        __syncthreads();
        #pragma unroll 4
        for (int k = 0; k < 32; k++) {
            float a0[4], a1[4], b0[4], b1[4];
            #pragma unroll
            for (int i = 0; i < 4; i++) { a0[i] = As[ty*4+i][k]; a1[i] = As[64+ty*4+i][k]; }
            #pragma unroll
            for (int j = 0; j < 4; j++) { b0[j] = Bs[tx*4+j][k]; b1[j] = Bs[64+tx*4+j][k]; }
            #pragma unroll
            for (int i = 0; i < 4; i++)
                #pragma unroll
                for (int j = 0; j < 4; j++) {
                    accA[i][j] = fmaf(a0[i], b0[j], accA[i][j]);
                    accB[i][j] = fmaf(a0[i], b1[j], accB[i][j]);
                    accC[i][j] = fmaf(a1[i], b0[j], accC[i][j]);
                    accD[i][j] = fmaf(a1[i], b1[j], accD[i][j]);
                }
        }
        __syncthreads();
    }

    #pragma unroll
    for (int i = 0; i < 4; i++) {
        int r0 = ty*4 + i, r1 = 64 + ty*4 + i;
        #pragma unroll
        for (int j = 0; j < 4; j++) {
            int q0 = tx*4 + j, q1 = 64 + tx*4 + j;
            H[r0*C + q0] = accA[i][j];
            H[r0*C + q1] = accB[i][j];
            H[r1*C + q0] = accC[i][j];
            H[r1*C + q1] = accD[i][j];
        }
    }
}

// ---------------- reduce: 39 per-(b,c) reductions over i, split 16 ways ----------------
__global__ __launch_bounds__(128) void reduce_kernel(
    const float* __restrict__ Wr, const float* __restrict__ Wsa,
    const float* __restrict__ Wo, const float* __restrict__ kn)
{
    const int b   = blockIdx.x;
    const int i0  = blockIdx.y * 8;
    const int c   = threadIdx.x;
    const float* G  = g_G + b*C*C;
    const float* Hr = g_H + (b*3 + 0)*C*C;
    const float* Hs = g_H + (b*3 + 1)*C*C;
    const float* Ho = g_H + (b*3 + 2)*C*C;

    __shared__ float kn_s[8][Ncls];
    __shared__ float s_s[8], u_s[8];
    {
        int t = threadIdx.x;
        int n = t & 15, ii = t >> 4;   // ii 0..7
        kn_s[ii][n] = kn[n*C + i0 + ii];
        if (t < 8) { s_s[t] = g_sx[b*C + i0 + t]; u_s[t] = g_u[i0 + t]; }
    }
    __syncthreads();

    float nxr2 = 0.f, dsa = 0.f, s2v = 0.f, csum = 0.f;
    float wr_s = 0.f, wsa_s = 0.f, wo_s = 0.f;
    float rel[Ncls], P[Ncls];
    #pragma unroll
    for (int n = 0; n < Ncls; n++) { rel[n] = 0.f; P[n] = 0.f; }

    #pragma unroll
    for (int ii = 0; ii < 8; ii++) {
        const int i = i0 + ii;
        float hr = Hr[i*C + c];
        float hs = Hs[i*C + c];
        float ho = Ho[i*C + c];
        float g  = G [i*C + c];
        float wri = Wr[c*C + i], wsi = Wsa[c*C + i], woi = Wo[c*C + i];
        float si = s_s[ii], ui = u_s[ii];
        nxr2 = fmaf(wri, hr, nxr2);
        dsa  = fmaf(wsi, hs, dsa);
        s2v  = fmaf(woi, ho, s2v);
        csum = fmaf(ui,  hs, csum);
        wr_s = fmaf(wri, si, wr_s);
        wsa_s= fmaf(wsi, si, wsa_s);
        wo_s = fmaf(woi, si, wo_s);
        #pragma unroll
        for (int n = 0; n < Ncls; n++) {
            float kv = kn_s[ii][n];
            rel[n] = fmaf(kv, hr, rel[n]);
            P[n]   = fmaf(kv, g,  P[n]);
        }
    }

    float* R = g_red + b*NQ*C;
    atomicAdd(&R[0*C + c], nxr2);
    atomicAdd(&R[1*C + c], dsa);
    atomicAdd(&R[2*C + c], s2v);
    atomicAdd(&R[3*C + c], csum);
    atomicAdd(&R[4*C + c], wr_s);
    atomicAdd(&R[5*C + c], wsa_s);
    atomicAdd(&R[6*C + c], wo_s);
    #pragma unroll
    for (int n = 0; n < Ncls; n++) {
        atomicAdd(&R[(7 + n)*C + c],  rel[n]);
        atomicAdd(&R[(23 + n)*C + c], P[n]);
    }
}

// ---------------- finalize ----------------
__global__ __launch_bounds__(128) void finalize_kernel(
    const float* __restrict__ bsa, const float* __restrict__ br,
    const float* __restrict__ kn,
    const float* __restrict__ Wo,  const float* __restrict__ bo,
    const float* __restrict__ alpha, const float* __restrict__ sigma)
{
    const int b = blockIdx.x;
    const int c = threadIdx.x;
    const float* R = g_red + b*NQ*C;
    const float hwf = 16384.f;

    __shared__ float s_sh[C], m_sh[C], s1_sh[C], s2_sh[C], A_sh[C], red_s[C];
    __shared__ float att_sh[Ncls][C];
    __shared__ float pn_sh[Ncls][C];
    __shared__ float nxn_sh[Ncls], kns_sh[Ncls], inv_sh[Ncls], minv_sh[Ncls];
    __shared__ float sc_us, sc_sb, sc_mx, sc_sum;

    float s_c = g_sx[b*C + c];
    s_sh[c] = s_c;
    float u_c = g_u[c];
    float bsc = bsa[c], brc = br[c], boc = bo[c];

    red_s[c] = u_c * s_c;
    __syncthreads();
    #pragma unroll
    for (int s = 64; s > 0; s >>= 1) { if (c < s) red_s[c] += red_s[c + s]; __syncthreads(); }
    if (c == 0) sc_us = red_s[0];
    __syncthreads();
    red_s[c] = bsc;
    __syncthreads();
    #pragma unroll
    for (int s = 64; s > 0; s >>= 1) { if (c < s) red_s[c] += red_s[c + s]; __syncthreads(); }
    if (c == 0) sc_sb = red_s[0];
    __syncthreads();

    #pragma unroll
    for (int n = 0; n < Ncls; n++) pn_sh[n][c] = R[(23 + n)*C + c] * kn[n*C + c];
    __syncthreads();
    if (c < Ncls) {
        float t = 0.f;
        #pragma unroll 4
        for (int k = 0; k < C; k++) t += pn_sh[c][k];
        nxn_sh[c] = sqrtf(t);
    }
    __syncthreads();
    #pragma unroll
    for (int n = 0; n < Ncls; n++) pn_sh[n][c] = kn[n*C + c] * s_sh[c];
    __syncthreads();
    if (c < Ncls) {
        float t = 0.f;
        #pragma unroll 4
        for (int k = 0; k < C; k++) t += pn_sh[c][k];
        kns_sh[c] = t;
    }
    __syncthreads();

    float wr_s = R[4*C + c], wsa_s = R[5*C + c], wo_s = R[6*C + c];
    float nxr2 = R[0*C + c] + 2.f*brc*wr_s + hwf*brc*brc;
    float nxr  = sqrtf(nxr2);
    float dsa  = R[1*C + c] + 2.f*bsc*wsa_s + hwf*bsc*bsc;
    float csum = R[3*C + c] + sc_sb*wsa_s + bsc*sc_us + hwf*sc_sb*bsc;
    m_sh[c]  = (csum - dsa) * (1.f/128.f);
    s1_sh[c] = wo_s + hwf*boc;
    s2_sh[c] = R[2*C + c] + 2.f*boc*wo_s + hwf*boc*boc;
    __syncthreads();

    red_s[c] = m_sh[c];
    __syncthreads();
    #pragma unroll
    for (int s = 64; s > 0; s >>= 1) { if (c < s) red_s[c] = fmaxf(red_s[c], red_s[c + s]); __syncthreads(); }
    if (c == 0) sc_mx = red_s[0];
    __syncthreads();
    float ex = expf(m_sh[c] - sc_mx);
    red_s[c] = ex;
    __syncthreads();
    #pragma unroll
    for (int s = 64; s > 0; s >>= 1) { if (c < s) red_s[c] += red_s[c + s]; __syncthreads(); }
    if (c == 0) sc_sum = red_s[0];
    __syncthreads();
    float regular = ex / sc_sum;

    {
        float rn[Ncls];
        float mxn = -1e30f;
        #pragma unroll
        for (int n = 0; n < Ncls; n++) {
            float r = R[(7 + n)*C + c] + brc * kns_sh[n];
            float al = fminf(fmaxf(alpha[n], 0.f), 1.f);
            rn[n] = r / (nxn_sh[n]*nxr + EPSF) + al * regular;
            mxn = fmaxf(mxn, rn[n]);
        }
        float se = 0.f;
        #pragma unroll
        for (int n = 0; n < Ncls; n++) { rn[n] = expf(rn[n] - mxn); se += rn[n]; }
        float ise = 1.f / se;
        #pragma unroll
        for (int n = 0; n < Ncls; n++) att_sh[n][c] = rn[n] * ise;
    }
    __syncthreads();

    if (c < Ncls) {
        int n = c;
        float cnt = 0.f, hot = 0.f, sq2 = 0.f;
        #pragma unroll 4
        for (int cc = 0; cc < C; cc++) {
            float a = att_sh[n][cc];
            cnt += a;
            hot = fmaf(a, s1_sh[cc], hot);
            sq2 = fmaf(a*a, s2_sh[cc], sq2);
        }
        cnt = cnt * hwf + EPSF;
        float mean = hot / cnt;
        float sq = sq2 - 2.f*mean*hot + mean*mean*(128.f*hwf);
        float stdv = sqrtf(sq / cnt);
        float inv = 1.f / (stdv + EPSF);
        inv_sh[n] = inv; minv_sh[n] = mean * inv;
    }
    __syncthreads();

    float sg = sigma[0];
    {
        float Av = 0.f, Bv = 0.f;
        #pragma unroll
        for (int n = 0; n < Ncls; n++) {
            float a = att_sh[n][c];
            Av = fmaf(a, inv_sh[n],  Av);
            Bv = fmaf(a, minv_sh[n], Bv);
        }
        A_sh[c] = Av;
        g_d[b*C + c] = sg * (Av * boc - Bv);
    }
    __syncthreads();

    // M = sigma*diag(A)*Wo  (identity handled exactly in out epilogue)
    #pragma unroll 4
    for (int t = c; t < C*C; t += 128) {
        int o = t >> 7;
        g_M[b*C*C + t] = sg * A_sh[o] * Wo[t];
    }
}

// ---------------- orthogonality loss ----------------
__global__ void loss_kernel(const float* __restrict__ kn, float* __restrict__ out, int out_size) {
    __shared__ float sym[Ncls][Ncls];
    __shared__ float partial[256];
    int tid = threadIdx.x;
    int i = tid >> 4, j = tid & 15;
    float dot = 0.f;
    #pragma unroll 4
    for (int k = 0; k < C; k++) dot = fmaf(kn[i*C + k], kn[j*C + k], dot);
    sym[i][j] = dot;
    __syncthreads();
    float nr = sqrtf(sym[i][i]) * sqrtf(sym[j][j]);
    float l = sym[i][j] / (nr + EPSF) - (i == j ? 1.f : 0.f);
    partial[tid] = l * l;
    __syncthreads();
    for (int s = 128; s > 0; s >>= 1) {
        if (tid < s) partial[tid] += partial[tid + s];
        __syncthreads();
    }
    if (tid == 0) {
        float loss = 0.1f * logf(partial[0] + 1.f);
        for (int idx = Bn*C*HW; idx < out_size; idx++) out[idx] = loss;
    }
}

// ---------------- out = x + Md@x + d via mma.sync tf32 (3-pass split, pipelined) ----------------
// grid (HW/128, Bn), block 256.
__global__ __launch_bounds__(256) void out_mma_kernel(const float* __restrict__ x,
                                                      float* __restrict__ out) {
    const int p0 = blockIdx.x * 128;
    const int b  = blockIdx.y;
    const int tid = threadIdx.x;
    const int w = tid >> 5, lane = tid & 31;
    const int gid = lane >> 2, tig = lane & 3;

    __shared__ uint32_t pool[9472];
    uint32_t* a_hi = pool;
    uint32_t* a_lo = pool + 2560;
    uint32_t* xs_hi = pool + 5120;
    uint32_t* xs_lo = pool + 7296;

    const float* Mb = g_M + b*C*C;
    const float* xb = x + (size_t)b*C*HW;

    float acc[16][4];
    #pragma unroll
    for (int t = 0; t < 16; t++) { acc[t][0]=0.f; acc[t][1]=0.f; acc[t][2]=0.f; acc[t][3]=0.f; }

    const int mc = tid >> 1, mseg = tid & 1;
    const int xk = tid >> 4, xsg = tid & 15;

    float4 vm[2], vx[2];
    #pragma unroll
    for (int j = 0; j < 2; j++) {
        vm[j] = *reinterpret_cast<const float4*>(Mb + mc*C + mseg*8 + j*4);
        vx[j] = *reinterpret_cast<const float4*>(xb + (size_t)xk*HW + p0 + xsg*8 + j*4);
    }

    for (int ch = 0; ch < 8; ch++) {
        __syncthreads();
        #pragma unroll
        for (int j = 0; j < 2; j++) {
            uint4 h, l;
            h.x = f2tf32(vm[j].x); l.x = f2tf32(vm[j].x - __uint_as_float(h.x));
            h.y = f2tf32(vm[j].y); l.y = f2tf32(vm[j].y - __uint_as_float(h.y));
            h.z = f2tf32(vm[j].z); l.z = f2tf32(vm[j].z - __uint_as_float(h.z));
            h.w = f2tf32(vm[j].w); l.w = f2tf32(vm[j].w - __uint_as_float(h.w));
            *reinterpret_cast<uint4*>(&a_hi[mc*20 + mseg*8 + j*4]) = h;
            *reinterpret_cast<uint4*>(&a_lo[mc*20 + mseg*8 + j*4]) = l;
        }
        #pragma unroll
        for (int j = 0; j < 2; j++) {
            uint4 h, l;
            h.x = f2tf32(vx[j].x); l.x = f2tf32(vx[j].x - __uint_as_float(h.x));
            h.y = f2tf32(vx[j].y); l.y = f2tf32(vx[j].y - __uint_as_float(h.y));
            h.z = f2tf32(vx[j].z); l.z = f2tf32(vx[j].z - __uint_as_float(h.z));
            h.w = f2tf32(vx[j].w); l.w = f2tf32(vx[j].w - __uint_as_float(h.w));
            *reinterpret_cast<uint4*>(&xs_hi[xk*136 + xsg*8 + j*4]) = h;
            *reinterpret_cast<uint4*>(&xs_lo[xk*136 + xsg*8 + j*4]) = l;
        }
        __syncthreads();
        // prefetch next chunk while MMAs run
        if (ch + 1 < 8) {
            const int k0n = (ch + 1)*16;
            #pragma unroll
            for (int j = 0; j < 2; j++) {
                vm[j] = *reinterpret_cast<const float4*>(Mb + mc*C + k0n + mseg*8 + j*4);
                vx[j] = *reinterpret_cast<const float4*>(xb + (size_t)(k0n + xk)*HW + p0 + xsg*8 + j*4);
            }
        }
        #pragma unroll
        for (int k8 = 0; k8 < 2; k8++) {
            const int kc = k8*8 + tig;
            uint32_t ah0 = a_hi[(w*16 + gid    )*20 + kc];
            uint32_t ah1 = a_hi[(w*16 + gid + 8)*20 + kc];
            uint32_t ah2 = a_hi[(w*16 + gid    )*20 + kc + 4];
            uint32_t ah3 = a_hi[(w*16 + gid + 8)*20 + kc + 4];
            uint32_t al0 = a_lo[(w*16 + gid    )*20 + kc];
            uint32_t al1 = a_lo[(w*16 + gid + 8)*20 + kc];
            uint32_t al2 = a_lo[(w*16 + gid    )*20 + kc + 4];
            uint32_t al3 = a_lo[(w*16 + gid + 8)*20 + kc + 4];
            #pragma unroll
            for (int t = 0; t < 16; t++) {
                uint32_t bh0 = xs_hi[ kc   *136 + t*8 + gid];
                uint32_t bh1 = xs_hi[(kc+4)*136 + t*8 + gid];
                uint32_t bl0 = xs_lo[ kc   *136 + t*8 + gid];
                uint32_t bl1 = xs_lo[(kc+4)*136 + t*8 + gid];
                MMA_TF32(acc[t], ah0, ah1, ah2, ah3, bh0, bh1);
                MMA_TF32(acc[t], ah0, ah1, ah2, ah3, bl0, bl1);
                MMA_TF32(acc[t], al0, al1, al2, al3, bh0, bh1);
            }
        }
    }

    // epilogue: out = x + delta + d
    float* stage = reinterpret_cast<float*>(pool);
    float* ob = out + (size_t)b*C*HW;
    const int cc = tid >> 1, sg2 = tid & 1;
    const float dc = g_d[b*C + cc];
    #pragma unroll
    for (int half = 0; half < 2; half++) {
        __syncthreads();
        #pragma unroll
        for (int t = 0; t < 8; t++) {
            int tt = half*8 + t;
            int colL = t*8 + 2*tig;
            stage[(w*16 + gid    )*68 + colL    ] = acc[tt][0];
            stage[(w*16 + gid    )*68 + colL + 1] = acc[tt][1];
            stage[(w*16 + gid + 8)*68 + colL    ] = acc[tt][2];
            stage[(w*16 + gid + 8)*68 + colL + 1] = acc[tt][3];
        }
        __syncthreads();
        #pragma unroll
        for (int j = 0; j < 8; j++) {
            int p = sg2*32 + j*4;
            float4 xv = *reinterpret_cast<const float4*>(xb + (size_t)cc*HW + p0 + half*64 + p);
            float4 sv = *reinterpret_cast<const float4*>(&stage[cc*68 + p]);
            float4 o;
            o.x = xv.x + sv.x + dc;
            o.y = xv.y + sv.y + dc;
            o.z = xv.z + sv.z + dc;
            o.w = xv.w + sv.w + dc;
            *reinterpret_cast<float4*>(ob + (size_t)cc*HW + p0 + half*64 + p) = o;
        }
    }
}

extern "C" void kernel_launch(void* const* d_in, const int* in_sizes, int n_in,
                              void* d_out, int out_size) {
    const float* x     = (const float*)d_in[0];
    const float* Wsa   = (const float*)d_in[1];
    const float* bsa   = (const float*)d_in[2];
    const float* Wr    = (const float*)d_in[3];
    const float* br    = (const float*)d_in[4];
    const float* kn    = (const float*)d_in[5];
    const float* Wo    = (const float*)d_in[6];
    const float* bo    = (const float*)d_in[7];
    const float* alpha = (const float*)d_in[8];
    const float* sigma = (const float*)d_in[9];
    float* out = (float*)d_out;

    zero_kernel<<<(Bn*C*C + 255) / 256, 256>>>(Wsa);
    gram_mma_kernel<<<dim3(KS, Bn), 256>>>(x);
    hgemm_kernel<<<dim3(3, Bn), 256>>>(Wr, Wsa, Wo);
    reduce_kernel<<<dim3(Bn, 16), 128>>>(Wr, Wsa, Wo, kn);
    finalize_kernel<<<Bn, 128>>>(bsa, br, kn, Wo, bo, alpha, sigma);
    loss_kernel<<<1, 256>>>(kn, out, out_size);
    out_mma_kernel<<<dim3(HW/128, Bn), 256>>>(x, out);
}

// round 7
// speedup vs baseline: 1.6478x; 1.6478x over previous
#include <cuda_runtime.h>
#include <math.h>
#include <stdint.h>

#define Bn 8
#define C 128
#define HW 16384
#define Ncls 16
#define EPSF 1e-7f
#define NQ 39
#define KS 16
#define KPC (HW/KS)   // 1024 pixels per gram CTA
#define GCHUNK 64

// ---------------- tf32 mma.sync helpers (baseline PTX, sm_80+) ----------------
__device__ __forceinline__ uint32_t f2tf32(float v) {
    uint32_t r; asm("cvt.rna.tf32.f32 %0, %1;" : "=r"(r) : "f"(v)); return r;
}
#define MMA_TF32(d, a0,a1,a2,a3, b0,b1) \
    asm volatile("mma.sync.aligned.m16n8k8.row.col.f32.tf32.tf32.f32 " \
        "{%0,%1,%2,%3}, {%4,%5,%6,%7}, {%8,%9}, {%0,%1,%2,%3};" \
        : "+f"((d)[0]), "+f"((d)[1]), "+f"((d)[2]), "+f"((d)[3]) \
        : "r"(a0), "r"(a1), "r"(a2), "r"(a3), "r"(b0), "r"(b1))

// ---------------- scratch ----------------
__device__ float g_G[Bn*C*C];
__device__ float g_sx[Bn*C];
__device__ float g_H[Bn*3*C*C];
__device__ float g_M[Bn*C*C];    // sigma*diag(A)*Wo (NO identity)
__device__ float g_d[Bn*C];
__device__ float g_red[Bn*NQ*C];
__device__ float g_u[C];

// ---------------- zero scratch + compute u ----------------
__global__ void zero_kernel(const float* __restrict__ Wsa) {
    int i = blockIdx.x * blockDim.x + threadIdx.x;
    if (i < Bn*C*C)  g_G[i] = 0.f;
    if (i < Bn*C)    g_sx[i] = 0.f;
    if (i < Bn*NQ*C) g_red[i] = 0.f;
    if (blockIdx.x == 0 && threadIdx.x < C) {
        float u = 0.f;
        #pragma unroll 4
        for (int r = 0; r < C; r++) u += Wsa[r*C + threadIdx.x];
        g_u[threadIdx.x] = u;
    }
}

// ---------------- Gram via mma.sync tf32: G[b] += X X^T (pipelined) ----------------
__global__ __launch_bounds__(256) void gram_mma_kernel(const float* __restrict__ x) {
    const int ks = blockIdx.x;
    const int b  = blockIdx.y;
    const int tid = threadIdx.x;
    const int w = tid >> 5, lane = tid & 31;
    const int gid = lane >> 2, tig = lane & 3;

    __shared__ uint32_t xt[C*68];   // [c][k] pitch 68, k=64

    float acc[16][4];
    #pragma unroll
    for (int t = 0; t < 16; t++) { acc[t][0]=0.f; acc[t][1]=0.f; acc[t][2]=0.f; acc[t][3]=0.f; }

    const int c   = tid >> 1;
    const int seg = tid & 1;                // 32 pixels each
    const float* xp = x + ((size_t)b*C + c)*HW + ks*KPC + seg*32;
    float ssum = 0.f;

    float4 v[8];
    #pragma unroll
    for (int j = 0; j < 8; j++) v[j] = *reinterpret_cast<const float4*>(xp + j*4);

    for (int it = 0; it < KPC/GCHUNK; it++) {   // 16 iterations of 64 pixels
        #pragma unroll
        for (int j = 0; j < 8; j++) ssum += (v[j].x + v[j].y) + (v[j].z + v[j].w);
        __syncthreads();
        #pragma unroll
        for (int j = 0; j < 8; j++) {
            uint4 u;
            u.x = f2tf32(v[j].x); u.y = f2tf32(v[j].y);
            u.z = f2tf32(v[j].z); u.w = f2tf32(v[j].w);
            *reinterpret_cast<uint4*>(&xt[c*68 + seg*32 + j*4]) = u;
        }
        __syncthreads();
        if (it + 1 < KPC/GCHUNK) {
            const float* np = xp + (size_t)(it + 1)*GCHUNK;
            #pragma unroll
            for (int j = 0; j < 8; j++) v[j] = *reinterpret_cast<const float4*>(np + j*4);
        }
        #pragma unroll
        for (int k8 = 0; k8 < 8; k8++) {
            const int kc = k8*8 + tig;
            uint32_t a0 = xt[(w*16 + gid    )*68 + kc];
            uint32_t a1 = xt[(w*16 + gid + 8)*68 + kc];
            uint32_t a2 = xt[(w*16 + gid    )*68 + kc + 4];
            uint32_t a3 = xt[(w*16 + gid + 8)*68 + kc + 4];
            #pragma unroll
            for (int t = 0; t < 16; t++) {
                uint32_t b0 = xt[(t*8 + gid)*68 + kc];
                uint32_t b1 = xt[(t*8 + gid)*68 + kc + 4];
                MMA_TF32(acc[t], a0, a1, a2, a3, b0, b1);
            }
        }
    }

    float* Gb = g_G + b*C*C;
    const int row0 = w*16 + gid;
    #pragma unroll
    for (int t = 0; t < 16; t++) {
        int col0 = t*8 + 2*tig;
        atomicAdd(&Gb[ row0   *C + col0    ], acc[t][0]);
        atomicAdd(&Gb[ row0   *C + col0 + 1], acc[t][1]);
        atomicAdd(&Gb[(row0+8)*C + col0    ], acc[t][2]);
        atomicAdd(&Gb[(row0+8)*C + col0 + 1], acc[t][3]);
    }
    atomicAdd(&g_sx[b*C + c], ssum);
}

// ---------------- H_m[b] = G[b] @ W_m^T ----------------
__global__ __launch_bounds__(256) void hgemm_kernel(const float* __restrict__ Wr,
                                                    const float* __restrict__ Wsa,
                                                    const float* __restrict__ Wo) {
    const int m = blockIdx.x;
    const int b = blockIdx.y;
    const float* W = (m == 0) ? Wr : (m == 1) ? Wsa : Wo;
    const float* G = g_G + b * C * C;
    float* H = g_H + (b * 3 + m) * C * C;

    __shared__ float As[C][33];
    __shared__ float Bs[C][33];
    const int tid = threadIdx.x;
    const int tx = tid & 15, ty = tid >> 4;
    const int kk = tid & 31, r0w = tid >> 5;

    float accA[4][4] = {}, accB[4][4] = {}, accC[4][4] = {}, accD[4][4] = {};

    for (int k0 = 0; k0 < C; k0 += 32) {
        #pragma unroll
        for (int i = 0; i < 16; i++) {
            int r = r0w + i * 8;
            As[r][kk] = G[r*C + k0 + kk];
            Bs[r][kk] = W[r*C + k0 + kk];
        }
        __syncthreads();
        #pragma unroll 4
        for (int k = 0; k < 32; k++) {
            float a0[4], a1[4], b0[4], b1[4];
            #pragma unroll
            for (int i = 0; i < 4; i++) { a0[i] = As[ty*4+i][k]; a1[i] = As[64+ty*4+i][k]; }
            #pragma unroll
            for (int j = 0; j < 4; j++) { b0[j] = Bs[tx*4+j][k]; b1[j] = Bs[64+tx*4+j][k]; }
            #pragma unroll
            for (int i = 0; i < 4; i++)
                #pragma unroll
                for (int j = 0; j < 4; j++) {
                    accA[i][j] = fmaf(a0[i], b0[j], accA[i][j]);
                    accB[i][j] = fmaf(a0[i], b1[j], accB[i][j]);
                    accC[i][j] = fmaf(a1[i], b0[j], accC[i][j]);
                    accD[i][j] = fmaf(a1[i], b1[j], accD[i][j]);
                }
        }
        __syncthreads();
    }

    #pragma unroll
    for (int i = 0; i < 4; i++) {
        int r0 = ty*4 + i, r1 = 64 + ty*4 + i;
        #pragma unroll
        for (int j = 0; j < 4; j++) {
            int q0 = tx*4 + j, q1 = 64 + tx*4 + j;
            H[r0*C + q0] = accA[i][j];
            H[r0*C + q1] = accB[i][j];
            H[r1*C + q0] = accC[i][j];
            H[r1*C + q1] = accD[i][j];
        }
    }
}

// ---------------- reduce: 39 per-(b,c) reductions over i, split 16 ways ----------------
__global__ __launch_bounds__(128) void reduce_kernel(
    const float* __restrict__ Wr, const float* __restrict__ Wsa,
    const float* __restrict__ Wo, const float* __restrict__ kn)
{
    const int b   = blockIdx.x;
    const int i0  = blockIdx.y * 8;
    const int c   = threadIdx.x;
    const float* G  = g_G + b*C*C;
    const float* Hr = g_H + (b*3 + 0)*C*C;
    const float* Hs = g_H + (b*3 + 1)*C*C;
    const float* Ho = g_H + (b*3 + 2)*C*C;

    __shared__ float kn_s[8][Ncls];
    __shared__ float s_s[8], u_s[8];
    {
        int t = threadIdx.x;
        int n = t & 15, ii = t >> 4;
        kn_s[ii][n] = kn[n*C + i0 + ii];
        if (t < 8) { s_s[t] = g_sx[b*C + i0 + t]; u_s[t] = g_u[i0 + t]; }
    }
    __syncthreads();

    float nxr2 = 0.f, dsa = 0.f, s2v = 0.f, csum = 0.f;
    float wr_s = 0.f, wsa_s = 0.f, wo_s = 0.f;
    float rel[Ncls], P[Ncls];
    #pragma unroll
    for (int n = 0; n < Ncls; n++) { rel[n] = 0.f; P[n] = 0.f; }

    #pragma unroll
    for (int ii = 0; ii < 8; ii++) {
        const int i = i0 + ii;
        float hr = Hr[i*C + c];
        float hs = Hs[i*C + c];
        float ho = Ho[i*C + c];
        float g  = G [i*C + c];
        float wri = Wr[c*C + i], wsi = Wsa[c*C + i], woi = Wo[c*C + i];
        float si = s_s[ii], ui = u_s[ii];
        nxr2 = fmaf(wri, hr, nxr2);
        dsa  = fmaf(wsi, hs, dsa);
        s2v  = fmaf(woi, ho, s2v);
        csum = fmaf(ui,  hs, csum);
        wr_s = fmaf(wri, si, wr_s);
        wsa_s= fmaf(wsi, si, wsa_s);
        wo_s = fmaf(woi, si, wo_s);
        #pragma unroll
        for (int n = 0; n < Ncls; n++) {
            float kv = kn_s[ii][n];
            rel[n] = fmaf(kv, hr, rel[n]);
            P[n]   = fmaf(kv, g,  P[n]);
        }
    }

    float* R = g_red + b*NQ*C;
    atomicAdd(&R[0*C + c], nxr2);
    atomicAdd(&R[1*C + c], dsa);
    atomicAdd(&R[2*C + c], s2v);
    atomicAdd(&R[3*C + c], csum);
    atomicAdd(&R[4*C + c], wr_s);
    atomicAdd(&R[5*C + c], wsa_s);
    atomicAdd(&R[6*C + c], wo_s);
    #pragma unroll
    for (int n = 0; n < Ncls; n++) {
        atomicAdd(&R[(7 + n)*C + c],  rel[n]);
        atomicAdd(&R[(23 + n)*C + c], P[n]);
    }
}

// ---------------- finalize ----------------
__global__ __launch_bounds__(128) void finalize_kernel(
    const float* __restrict__ bsa, const float* __restrict__ br,
    const float* __restrict__ kn,
    const float* __restrict__ Wo,  const float* __restrict__ bo,
    const float* __restrict__ alpha, const float* __restrict__ sigma)
{
    const int b = blockIdx.x;
    const int c = threadIdx.x;
    const float* R = g_red + b*NQ*C;
    const float hwf = 16384.f;

    __shared__ float s_sh[C], m_sh[C], s1_sh[C], s2_sh[C], A_sh[C], red_s[C];
    __shared__ float att_sh[Ncls][C];
    __shared__ float pn_sh[Ncls][C];
    __shared__ float nxn_sh[Ncls], kns_sh[Ncls], inv_sh[Ncls], minv_sh[Ncls];
    __shared__ float sc_us, sc_sb, sc_mx, sc_sum;

    float s_c = g_sx[b*C + c];
    s_sh[c] = s_c;
    float u_c = g_u[c];
    float bsc = bsa[c], brc = br[c], boc = bo[c];

    red_s[c] = u_c * s_c;
    __syncthreads();
    #pragma unroll
    for (int s = 64; s > 0; s >>= 1) { if (c < s) red_s[c] += red_s[c + s]; __syncthreads(); }
    if (c == 0) sc_us = red_s[0];
    __syncthreads();
    red_s[c] = bsc;
    __syncthreads();
    #pragma unroll
    for (int s = 64; s > 0; s >>= 1) { if (c < s) red_s[c] += red_s[c + s]; __syncthreads(); }
    if (c == 0) sc_sb = red_s[0];
    __syncthreads();

    #pragma unroll
    for (int n = 0; n < Ncls; n++) pn_sh[n][c] = R[(23 + n)*C + c] * kn[n*C + c];
    __syncthreads();
    if (c < Ncls) {
        float t = 0.f;
        #pragma unroll 4
        for (int k = 0; k < C; k++) t += pn_sh[c][k];
        nxn_sh[c] = sqrtf(t);
    }
    __syncthreads();
    #pragma unroll
    for (int n = 0; n < Ncls; n++) pn_sh[n][c] = kn[n*C + c] * s_sh[c];
    __syncthreads();
    if (c < Ncls) {
        float t = 0.f;
        #pragma unroll 4
        for (int k = 0; k < C; k++) t += pn_sh[c][k];
        kns_sh[c] = t;
    }
    __syncthreads();

    float wr_s = R[4*C + c], wsa_s = R[5*C + c], wo_s = R[6*C + c];
    float nxr2 = R[0*C + c] + 2.f*brc*wr_s + hwf*brc*brc;
    float nxr  = sqrtf(nxr2);
    float dsa  = R[1*C + c] + 2.f*bsc*wsa_s + hwf*bsc*bsc;
    float csum = R[3*C + c] + sc_sb*wsa_s + bsc*sc_us + hwf*sc_sb*bsc;
    m_sh[c]  = (csum - dsa) * (1.f/128.f);
    s1_sh[c] = wo_s + hwf*boc;
    s2_sh[c] = R[2*C + c] + 2.f*boc*wo_s + hwf*boc*boc;
    __syncthreads();

    red_s[c] = m_sh[c];
    __syncthreads();
    #pragma unroll
    for (int s = 64; s > 0; s >>= 1) { if (c < s) red_s[c] = fmaxf(red_s[c], red_s[c + s]); __syncthreads(); }
    if (c == 0) sc_mx = red_s[0];
    __syncthreads();
    float ex = expf(m_sh[c] - sc_mx);
    red_s[c] = ex;
    __syncthreads();
    #pragma unroll
    for (int s = 64; s > 0; s >>= 1) { if (c < s) red_s[c] += red_s[c + s]; __syncthreads(); }
    if (c == 0) sc_sum = red_s[0];
    __syncthreads();
    float regular = ex / sc_sum;

    {
        float rn[Ncls];
        float mxn = -1e30f;
        #pragma unroll
        for (int n = 0; n < Ncls; n++) {
            float r = R[(7 + n)*C + c] + brc * kns_sh[n];
            float al = fminf(fmaxf(alpha[n], 0.f), 1.f);
            rn[n] = r / (nxn_sh[n]*nxr + EPSF) + al * regular;
            mxn = fmaxf(mxn, rn[n]);
        }
        float se = 0.f;
        #pragma unroll
        for (int n = 0; n < Ncls; n++) { rn[n] = expf(rn[n] - mxn); se += rn[n]; }
        float ise = 1.f / se;
        #pragma unroll
        for (int n = 0; n < Ncls; n++) att_sh[n][c] = rn[n] * ise;
    }
    __syncthreads();

    if (c < Ncls) {
        int n = c;
        float cnt = 0.f, hot = 0.f, sq2 = 0.f;
        #pragma unroll 4
        for (int cc = 0; cc < C; cc++) {
            float a = att_sh[n][cc];
            cnt += a;
            hot = fmaf(a, s1_sh[cc], hot);
            sq2 = fmaf(a*a, s2_sh[cc], sq2);
        }
        cnt = cnt * hwf + EPSF;
        float mean = hot / cnt;
        float sq = sq2 - 2.f*mean*hot + mean*mean*(128.f*hwf);
        float stdv = sqrtf(sq / cnt);
        float inv = 1.f / (stdv + EPSF);
        inv_sh[n] = inv; minv_sh[n] = mean * inv;
    }
    __syncthreads();

    float sg = sigma[0];
    {
        float Av = 0.f, Bv = 0.f;
        #pragma unroll
        for (int n = 0; n < Ncls; n++) {
            float a = att_sh[n][c];
            Av = fmaf(a, inv_sh[n],  Av);
            Bv = fmaf(a, minv_sh[n], Bv);
        }
        A_sh[c] = Av;
        g_d[b*C + c] = sg * (Av * boc - Bv);
    }
    __syncthreads();

    #pragma unroll 4
    for (int t = c; t < C*C; t += 128) {
        int o = t >> 7;
        g_M[b*C*C + t] = sg * A_sh[o] * Wo[t];
    }
}

// ---------------- orthogonality loss ----------------
__global__ void loss_kernel(const float* __restrict__ kn, float* __restrict__ out, int out_size) {
    __shared__ float sym[Ncls][Ncls];
    __shared__ float partial[256];
    int tid = threadIdx.x;
    int i = tid >> 4, j = tid & 15;
    float dot = 0.f;
    #pragma unroll 4
    for (int k = 0; k < C; k++) dot = fmaf(kn[i*C + k], kn[j*C + k], dot);
    sym[i][j] = dot;
    __syncthreads();
    float nr = sqrtf(sym[i][i]) * sqrtf(sym[j][j]);
    float l = sym[i][j] / (nr + EPSF) - (i == j ? 1.f : 0.f);
    partial[tid] = l * l;
    __syncthreads();
    for (int s = 128; s > 0; s >>= 1) {
        if (tid < s) partial[tid] += partial[tid + s];
        __syncthreads();
    }
    if (tid == 0) {
        float loss = 0.1f * logf(partial[0] + 1.f);
        for (int idx = Bn*C*HW; idx < out_size; idx++) out[idx] = loss;
    }
}

// ---------------- out = x + Mhi@(x_hi+x_lo) + d via mma.sync tf32 (2-pass, pipelined) ----------------
// grid (HW/128, Bn), block 256.
__global__ __launch_bounds__(256) void out_mma_kernel(const float* __restrict__ x,
                                                      float* __restrict__ out) {
    const int p0 = blockIdx.x * 128;
    const int b  = blockIdx.y;
    const int tid = threadIdx.x;
    const int w = tid >> 5, lane = tid & 31;
    const int gid = lane >> 2, tig = lane & 3;

    // pool: a_hi [128][20] @0, x_hi [16][136] @2560, x_lo @4736 (6912 words)
    // epilogue reuses @0 as float stage [128][68] (8704 words)
    __shared__ uint32_t pool[8704];
    uint32_t* a_hi = pool;
    uint32_t* xs_hi = pool + 2560;
    uint32_t* xs_lo = pool + 4736;

    const float* Mb = g_M + b*C*C;
    const float* xb = x + (size_t)b*C*HW;

    float acc[16][4];
    #pragma unroll
    for (int t = 0; t < 16; t++) { acc[t][0]=0.f; acc[t][1]=0.f; acc[t][2]=0.f; acc[t][3]=0.f; }

    const int mc = tid >> 1, mseg = tid & 1;
    const int xk = tid >> 4, xsg = tid & 15;

    float4 vm[2], vx[2];
    #pragma unroll
    for (int j = 0; j < 2; j++) {
        vm[j] = *reinterpret_cast<const float4*>(Mb + mc*C + mseg*8 + j*4);
        vx[j] = *reinterpret_cast<const float4*>(xb + (size_t)xk*HW + p0 + xsg*8 + j*4);
    }

    for (int ch = 0; ch < 8; ch++) {
        __syncthreads();
        #pragma unroll
        for (int j = 0; j < 2; j++) {
            uint4 h;
            h.x = f2tf32(vm[j].x); h.y = f2tf32(vm[j].y);
            h.z = f2tf32(vm[j].z); h.w = f2tf32(vm[j].w);
            *reinterpret_cast<uint4*>(&a_hi[mc*20 + mseg*8 + j*4]) = h;
        }
        #pragma unroll
        for (int j = 0; j < 2; j++) {
            uint4 h, l;
            h.x = f2tf32(vx[j].x); l.x = f2tf32(vx[j].x - __uint_as_float(h.x));
            h.y = f2tf32(vx[j].y); l.y = f2tf32(vx[j].y - __uint_as_float(h.y));
            h.z = f2tf32(vx[j].z); l.z = f2tf32(vx[j].z - __uint_as_float(h.z));
            h.w = f2tf32(vx[j].w); l.w = f2tf32(vx[j].w - __uint_as_float(h.w));
            *reinterpret_cast<uint4*>(&xs_hi[xk*136 + xsg*8 + j*4]) = h;
            *reinterpret_cast<uint4*>(&xs_lo[xk*136 + xsg*8 + j*4]) = l;
        }
        __syncthreads();
        // prefetch next chunk while MMAs run
        if (ch + 1 < 8) {
            const int k0n = (ch + 1)*16;
            #pragma unroll
            for (int j = 0; j < 2; j++) {
                vm[j] = *reinterpret_cast<const float4*>(Mb + mc*C + k0n + mseg*8 + j*4);
                vx[j] = *reinterpret_cast<const float4*>(xb + (size_t)(k0n + xk)*HW + p0 + xsg*8 + j*4);
            }
        }
        #pragma unroll
        for (int k8 = 0; k8 < 2; k8++) {
            const int kc = k8*8 + tig;
            uint32_t ah0 = a_hi[(w*16 + gid    )*20 + kc];
            uint32_t ah1 = a_hi[(w*16 + gid + 8)*20 + kc];
            uint32_t ah2 = a_hi[(w*16 + gid    )*20 + kc + 4];
            uint32_t ah3 = a_hi[(w*16 + gid + 8)*20 + kc + 4];
            #pragma unroll
            for (int t = 0; t < 16; t++) {
                uint32_t bh0 = xs_hi[ kc   *136 + t*8 + gid];
                uint32_t bh1 = xs_hi[(kc+4)*136 + t*8 + gid];
                uint32_t bl0 = xs_lo[ kc   *136 + t*8 + gid];
                uint32_t bl1 = xs_lo[(kc+4)*136 + t*8 + gid];
                MMA_TF32(acc[t], ah0, ah1, ah2, ah3, bh0, bh1);
                MMA_TF32(acc[t], ah0, ah1, ah2, ah3, bl0, bl1);
            }
        }
    }

    // epilogue: out = x + delta + d
    float* stage = reinterpret_cast<float*>(pool);
    float* ob = out + (size_t)b*C*HW;
    const int cc = tid >> 1, sg2 = tid & 1;
    const float dc = g_d[b*C + cc];
    #pragma unroll
    for (int half = 0; half < 2; half++) {
        __syncthreads();
        #pragma unroll
        for (int t = 0; t < 8; t++) {
            int tt = half*8 + t;
            int colL = t*8 + 2*tig;
            stage[(w*16 + gid    )*68 + colL    ] = acc[tt][0];
            stage[(w*16 + gid    )*68 + colL + 1] = acc[tt][1];
            stage[(w*16 + gid + 8)*68 + colL    ] = acc[tt][2];
            stage[(w*16 + gid + 8)*68 + colL + 1] = acc[tt][3];
        }
        __syncthreads();
        #pragma unroll
        for (int j = 0; j < 8; j++) {
            int p = sg2*32 + j*4;
            float4 xv = *reinterpret_cast<const float4*>(xb + (size_t)cc*HW + p0 + half*64 + p);
            float4 sv = *reinterpret_cast<const float4*>(&stage[cc*68 + p]);
            float4 o;
            o.x = xv.x + sv.x + dc;
            o.y = xv.y + sv.y + dc;
            o.z = xv.z + sv.z + dc;
            o.w = xv.w + sv.w + dc;
            *reinterpret_cast<float4*>(ob + (size_t)cc*HW + p0 + half*64 + p) = o;
        }
    }
}

extern "C" void kernel_launch(void* const* d_in, const int* in_sizes, int n_in,
                              void* d_out, int out_size) {
    const float* x     = (const float*)d_in[0];
    const float* Wsa   = (const float*)d_in[1];
    const float* bsa   = (const float*)d_in[2];
    const float* Wr    = (const float*)d_in[3];
    const float* br    = (const float*)d_in[4];
    const float* kn    = (const float*)d_in[5];
    const float* Wo    = (const float*)d_in[6];
    const float* bo    = (const float*)d_in[7];
    const float* alpha = (const float*)d_in[8];
    const float* sigma = (const float*)d_in[9];
    float* out = (float*)d_out;

    zero_kernel<<<(Bn*C*C + 255) / 256, 256>>>(Wsa);
    gram_mma_kernel<<<dim3(KS, Bn), 256>>>(x);
    hgemm_kernel<<<dim3(3, Bn), 256>>>(Wr, Wsa, Wo);
    reduce_kernel<<<dim3(Bn, 16), 128>>>(Wr, Wsa, Wo, kn);
    finalize_kernel<<<Bn, 128>>>(bsa, br, kn, Wo, bo, alpha, sigma);
    loss_kernel<<<1, 256>>>(kn, out, out_size);
    out_mma_kernel<<<dim3(HW/128, Bn), 256>>>(x, out);
}

// round 8
// speedup vs baseline: 1.8712x; 1.1355x over previous
#include <cuda_runtime.h>
#include <math.h>
#include <stdint.h>

#define Bn 8
#define C 128
#define HW 16384
#define Ncls 16
#define EPSF 1e-7f
#define NQ 39
#define KS 16
#define KPC (HW/KS)   // 1024 pixels per gram CTA
#define GCHUNK 64

// ---------------- tf32 mma.sync helpers (baseline PTX, sm_80+) ----------------
__device__ __forceinline__ uint32_t f2tf32(float v) {
    uint32_t r; asm("cvt.rna.tf32.f32 %0, %1;" : "=r"(r) : "f"(v)); return r;
}
#define MMA_TF32(d, a0,a1,a2,a3, b0,b1) \
    asm volatile("mma.sync.aligned.m16n8k8.row.col.f32.tf32.tf32.f32 " \
        "{%0,%1,%2,%3}, {%4,%5,%6,%7}, {%8,%9}, {%0,%1,%2,%3};" \
        : "+f"((d)[0]), "+f"((d)[1]), "+f"((d)[2]), "+f"((d)[3]) \
        : "r"(a0), "r"(a1), "r"(a2), "r"(a3), "r"(b0), "r"(b1))

// ---------------- scratch ----------------
__device__ float g_G[Bn*C*C];
__device__ float g_sx[Bn*C];
__device__ float g_H[Bn*3*C*C];
__device__ float g_M[Bn*C*C];    // sigma*diag(A)*Wo, PRE-ROUNDED to tf32 bits
__device__ float g_d[Bn*C];
__device__ float g_red[Bn*NQ*C];
__device__ float g_u[C];

// ---------------- zero scratch + compute u ----------------
__global__ void zero_kernel(const float* __restrict__ Wsa) {
    int i = blockIdx.x * blockDim.x + threadIdx.x;
    if (i < Bn*C*C)  g_G[i] = 0.f;
    if (i < Bn*C)    g_sx[i] = 0.f;
    if (i < Bn*NQ*C) g_red[i] = 0.f;
    if (blockIdx.x == 0 && threadIdx.x < C) {
        float u = 0.f;
        #pragma unroll 4
        for (int r = 0; r < C; r++) u += Wsa[r*C + threadIdx.x];
        g_u[threadIdx.x] = u;
    }
}

// ---------------- Gram via mma.sync tf32: G[b] += X X^T (pipelined) ----------------
__global__ __launch_bounds__(256) void gram_mma_kernel(const float* __restrict__ x) {
    const int ks = blockIdx.x;
    const int b  = blockIdx.y;
    const int tid = threadIdx.x;
    const int w = tid >> 5, lane = tid & 31;
    const int gid = lane >> 2, tig = lane & 3;

    __shared__ uint32_t xt[C*68];   // [c][k] pitch 68, k=64

    float acc[16][4];
    #pragma unroll
    for (int t = 0; t < 16; t++) { acc[t][0]=0.f; acc[t][1]=0.f; acc[t][2]=0.f; acc[t][3]=0.f; }

    const int c   = tid >> 1;
    const int seg = tid & 1;
    const float* xp = x + ((size_t)b*C + c)*HW + ks*KPC + seg*32;
    float ssum = 0.f;

    float4 v[8];
    #pragma unroll
    for (int j = 0; j < 8; j++) v[j] = *reinterpret_cast<const float4*>(xp + j*4);

    for (int it = 0; it < KPC/GCHUNK; it++) {
        #pragma unroll
        for (int j = 0; j < 8; j++) ssum += (v[j].x + v[j].y) + (v[j].z + v[j].w);
        __syncthreads();
        #pragma unroll
        for (int j = 0; j < 8; j++) {
            uint4 u;
            u.x = f2tf32(v[j].x); u.y = f2tf32(v[j].y);
            u.z = f2tf32(v[j].z); u.w = f2tf32(v[j].w);
            *reinterpret_cast<uint4*>(&xt[c*68 + seg*32 + j*4]) = u;
        }
        __syncthreads();
        if (it + 1 < KPC/GCHUNK) {
            const float* np = xp + (size_t)(it + 1)*GCHUNK;
            #pragma unroll
            for (int j = 0; j < 8; j++) v[j] = *reinterpret_cast<const float4*>(np + j*4);
        }
        #pragma unroll
        for (int k8 = 0; k8 < 8; k8++) {
            const int kc = k8*8 + tig;
            uint32_t a0 = xt[(w*16 + gid    )*68 + kc];
            uint32_t a1 = xt[(w*16 + gid + 8)*68 + kc];
            uint32_t a2 = xt[(w*16 + gid    )*68 + kc + 4];
            uint32_t a3 = xt[(w*16 + gid + 8)*68 + kc + 4];
            #pragma unroll
            for (int t = 0; t < 16; t++) {
                uint32_t b0 = xt[(t*8 + gid)*68 + kc];
                uint32_t b1 = xt[(t*8 + gid)*68 + kc + 4];
                MMA_TF32(acc[t], a0, a1, a2, a3, b0, b1);
            }
        }
    }

    float* Gb = g_G + b*C*C;
    const int row0 = w*16 + gid;
    #pragma unroll
    for (int t = 0; t < 16; t++) {
        int col0 = t*8 + 2*tig;
        atomicAdd(&Gb[ row0   *C + col0    ], acc[t][0]);
        atomicAdd(&Gb[ row0   *C + col0 + 1], acc[t][1]);
        atomicAdd(&Gb[(row0+8)*C + col0    ], acc[t][2]);
        atomicAdd(&Gb[(row0+8)*C + col0 + 1], acc[t][3]);
    }
    atomicAdd(&g_sx[b*C + c], ssum);
}

// ---------------- H_m[b] = G[b] @ W_m^T ----------------
__global__ __launch_bounds__(256) void hgemm_kernel(const float* __restrict__ Wr,
                                                    const float* __restrict__ Wsa,
                                                    const float* __restrict__ Wo) {
    const int m = blockIdx.x;
    const int b = blockIdx.y;
    const float* W = (m == 0) ? Wr : (m == 1) ? Wsa : Wo;
    const float* G = g_G + b * C * C;
    float* H = g_H + (b * 3 + m) * C * C;

    __shared__ float As[C][33];
    __shared__ float Bs[C][33];
    const int tid = threadIdx.x;
    const int tx = tid & 15, ty = tid >> 4;
    const int kk = tid & 31, r0w = tid >> 5;

    float accA[4][4] = {}, accB[4][4] = {}, accC[4][4] = {}, accD[4][4] = {};

    for (int k0 = 0; k0 < C; k0 += 32) {
        #pragma unroll
        for (int i = 0; i < 16; i++) {
            int r = r0w + i * 8;
            As[r][kk] = G[r*C + k0 + kk];
            Bs[r][kk] = W[r*C + k0 + kk];
        }
        __syncthreads();
        #pragma unroll 4
        for (int k = 0; k < 32; k++) {
            float a0[4], a1[4], b0[4], b1[4];
            #pragma unroll
            for (int i = 0; i < 4; i++) { a0[i] = As[ty*4+i][k]; a1[i] = As[64+ty*4+i][k]; }
            #pragma unroll
            for (int j = 0; j < 4; j++) { b0[j] = Bs[tx*4+j][k]; b1[j] = Bs[64+tx*4+j][k]; }
            #pragma unroll
            for (int i = 0; i < 4; i++)
                #pragma unroll
                for (int j = 0; j < 4; j++) {
                    accA[i][j] = fmaf(a0[i], b0[j], accA[i][j]);
                    accB[i][j] = fmaf(a0[i], b1[j], accB[i][j]);
                    accC[i][j] = fmaf(a1[i], b0[j], accC[i][j]);
                    accD[i][j] = fmaf(a1[i], b1[j], accD[i][j]);
                }
        }
        __syncthreads();
    }

    #pragma unroll
    for (int i = 0; i < 4; i++) {
        int r0 = ty*4 + i, r1 = 64 + ty*4 + i;
        #pragma unroll
        for (int j = 0; j < 4; j++) {
            int q0 = tx*4 + j, q1 = 64 + tx*4 + j;
            H[r0*C + q0] = accA[i][j];
            H[r0*C + q1] = accB[i][j];
            H[r1*C + q0] = accC[i][j];
            H[r1*C + q1] = accD[i][j];
        }
    }
}

// ---------------- reduce: 39 per-(b,c) reductions over i, split 16 ways ----------------
__global__ __launch_bounds__(128) void reduce_kernel(
    const float* __restrict__ Wr, const float* __restrict__ Wsa,
    const float* __restrict__ Wo, const float* __restrict__ kn)
{
    const int b   = blockIdx.x;
    const int i0  = blockIdx.y * 8;
    const int c   = threadIdx.x;
    const float* G  = g_G + b*C*C;
    const float* Hr = g_H + (b*3 + 0)*C*C;
    const float* Hs = g_H + (b*3 + 1)*C*C;
    const float* Ho = g_H + (b*3 + 2)*C*C;

    __shared__ float kn_s[8][Ncls];
    __shared__ float s_s[8], u_s[8];
    {
        int t = threadIdx.x;
        int n = t & 15, ii = t >> 4;
        kn_s[ii][n] = kn[n*C + i0 + ii];
        if (t < 8) { s_s[t] = g_sx[b*C + i0 + t]; u_s[t] = g_u[i0 + t]; }
    }
    __syncthreads();

    float nxr2 = 0.f, dsa = 0.f, s2v = 0.f, csum = 0.f;
    float wr_s = 0.f, wsa_s = 0.f, wo_s = 0.f;
    float rel[Ncls], P[Ncls];
    #pragma unroll
    for (int n = 0; n < Ncls; n++) { rel[n] = 0.f; P[n] = 0.f; }

    #pragma unroll
    for (int ii = 0; ii < 8; ii++) {
        const int i = i0 + ii;
        float hr = Hr[i*C + c];
        float hs = Hs[i*C + c];
        float ho = Ho[i*C + c];
        float g  = G [i*C + c];
        float wri = Wr[c*C + i], wsi = Wsa[c*C + i], woi = Wo[c*C + i];
        float si = s_s[ii], ui = u_s[ii];
        nxr2 = fmaf(wri, hr, nxr2);
        dsa  = fmaf(wsi, hs, dsa);
        s2v  = fmaf(woi, ho, s2v);
        csum = fmaf(ui,  hs, csum);
        wr_s = fmaf(wri, si, wr_s);
        wsa_s= fmaf(wsi, si, wsa_s);
        wo_s = fmaf(woi, si, wo_s);
        #pragma unroll
        for (int n = 0; n < Ncls; n++) {
            float kv = kn_s[ii][n];
            rel[n] = fmaf(kv, hr, rel[n]);
            P[n]   = fmaf(kv, g,  P[n]);
        }
    }

    float* R = g_red + b*NQ*C;
    atomicAdd(&R[0*C + c], nxr2);
    atomicAdd(&R[1*C + c], dsa);
    atomicAdd(&R[2*C + c], s2v);
    atomicAdd(&R[3*C + c], csum);
    atomicAdd(&R[4*C + c], wr_s);
    atomicAdd(&R[5*C + c], wsa_s);
    atomicAdd(&R[6*C + c], wo_s);
    #pragma unroll
    for (int n = 0; n < Ncls; n++) {
        atomicAdd(&R[(7 + n)*C + c],  rel[n]);
        atomicAdd(&R[(23 + n)*C + c], P[n]);
    }
}

// ---------------- finalize ----------------
__global__ __launch_bounds__(128) void finalize_kernel(
    const float* __restrict__ bsa, const float* __restrict__ br,
    const float* __restrict__ kn,
    const float* __restrict__ Wo,  const float* __restrict__ bo,
    const float* __restrict__ alpha, const float* __restrict__ sigma)
{
    const int b = blockIdx.x;
    const int c = threadIdx.x;
    const float* R = g_red + b*NQ*C;
    const float hwf = 16384.f;

    __shared__ float s_sh[C], m_sh[C], s1_sh[C], s2_sh[C], A_sh[C], red_s[C];
    __shared__ float att_sh[Ncls][C];
    __shared__ float pn_sh[Ncls][C];
    __shared__ float nxn_sh[Ncls], kns_sh[Ncls], inv_sh[Ncls], minv_sh[Ncls];
    __shared__ float sc_us, sc_sb, sc_mx, sc_sum;

    float s_c = g_sx[b*C + c];
    s_sh[c] = s_c;
    float u_c = g_u[c];
    float bsc = bsa[c], brc = br[c], boc = bo[c];

    red_s[c] = u_c * s_c;
    __syncthreads();
    #pragma unroll
    for (int s = 64; s > 0; s >>= 1) { if (c < s) red_s[c] += red_s[c + s]; __syncthreads(); }
    if (c == 0) sc_us = red_s[0];
    __syncthreads();
    red_s[c] = bsc;
    __syncthreads();
    #pragma unroll
    for (int s = 64; s > 0; s >>= 1) { if (c < s) red_s[c] += red_s[c + s]; __syncthreads(); }
    if (c == 0) sc_sb = red_s[0];
    __syncthreads();

    #pragma unroll
    for (int n = 0; n < Ncls; n++) pn_sh[n][c] = R[(23 + n)*C + c] * kn[n*C + c];
    __syncthreads();
    if (c < Ncls) {
        float t = 0.f;
        #pragma unroll 4
        for (int k = 0; k < C; k++) t += pn_sh[c][k];
        nxn_sh[c] = sqrtf(t);
    }
    __syncthreads();
    #pragma unroll
    for (int n = 0; n < Ncls; n++) pn_sh[n][c] = kn[n*C + c] * s_sh[c];
    __syncthreads();
    if (c < Ncls) {
        float t = 0.f;
        #pragma unroll 4
        for (int k = 0; k < C; k++) t += pn_sh[c][k];
        kns_sh[c] = t;
    }
    __syncthreads();

    float wr_s = R[4*C + c], wsa_s = R[5*C + c], wo_s = R[6*C + c];
    float nxr2 = R[0*C + c] + 2.f*brc*wr_s + hwf*brc*brc;
    float nxr  = sqrtf(nxr2);
    float dsa  = R[1*C + c] + 2.f*bsc*wsa_s + hwf*bsc*bsc;
    float csum = R[3*C + c] + sc_sb*wsa_s + bsc*sc_us + hwf*sc_sb*bsc;
    m_sh[c]  = (csum - dsa) * (1.f/128.f);
    s1_sh[c] = wo_s + hwf*boc;
    s2_sh[c] = R[2*C + c] + 2.f*boc*wo_s + hwf*boc*boc;
    __syncthreads();

    red_s[c] = m_sh[c];
    __syncthreads();
    #pragma unroll
    for (int s = 64; s > 0; s >>= 1) { if (c < s) red_s[c] = fmaxf(red_s[c], red_s[c + s]); __syncthreads(); }
    if (c == 0) sc_mx = red_s[0];
    __syncthreads();
    float ex = expf(m_sh[c] - sc_mx);
    red_s[c] = ex;
    __syncthreads();
    #pragma unroll
    for (int s = 64; s > 0; s >>= 1) { if (c < s) red_s[c] += red_s[c + s]; __syncthreads(); }
    if (c == 0) sc_sum = red_s[0];
    __syncthreads();
    float regular = ex / sc_sum;

    {
        float rn[Ncls];
        float mxn = -1e30f;
        #pragma unroll
        for (int n = 0; n < Ncls; n++) {
            float r = R[(7 + n)*C + c] + brc * kns_sh[n];
            float al = fminf(fmaxf(alpha[n], 0.f), 1.f);
            rn[n] = r / (nxn_sh[n]*nxr + EPSF) + al * regular;
            mxn = fmaxf(mxn, rn[n]);
        }
        float se = 0.f;
        #pragma unroll
        for (int n = 0; n < Ncls; n++) { rn[n] = expf(rn[n] - mxn); se += rn[n]; }
        float ise = 1.f / se;
        #pragma unroll
        for (int n = 0; n < Ncls; n++) att_sh[n][c] = rn[n] * ise;
    }
    __syncthreads();

    if (c < Ncls) {
        int n = c;
        float cnt = 0.f, hot = 0.f, sq2 = 0.f;
        #pragma unroll 4
        for (int cc = 0; cc < C; cc++) {
            float a = att_sh[n][cc];
            cnt += a;
            hot = fmaf(a, s1_sh[cc], hot);
            sq2 = fmaf(a*a, s2_sh[cc], sq2);
        }
        cnt = cnt * hwf + EPSF;
        float mean = hot / cnt;
        float sq = sq2 - 2.f*mean*hot + mean*mean*(128.f*hwf);
        float stdv = sqrtf(sq / cnt);
        float inv = 1.f / (stdv + EPSF);
        inv_sh[n] = inv; minv_sh[n] = mean * inv;
    }
    __syncthreads();

    float sg = sigma[0];
    {
        float Av = 0.f, Bv = 0.f;
        #pragma unroll
        for (int n = 0; n < Ncls; n++) {
            float a = att_sh[n][c];
            Av = fmaf(a, inv_sh[n],  Av);
            Bv = fmaf(a, minv_sh[n], Bv);
        }
        A_sh[c] = Av;
        g_d[b*C + c] = sg * (Av * boc - Bv);
    }
    __syncthreads();

    // M = sigma*diag(A)*Wo, pre-rounded to tf32 (M is only ever used as the hi operand)
    #pragma unroll 4
    for (int t = c; t < C*C; t += 128) {
        int o = t >> 7;
        g_M[b*C*C + t] = __uint_as_float(f2tf32(sg * A_sh[o] * Wo[t]));
    }
}

// ---------------- orthogonality loss ----------------
__global__ void loss_kernel(const float* __restrict__ kn, float* __restrict__ out, int out_size) {
    __shared__ float sym[Ncls][Ncls];
    __shared__ float partial[256];
    int tid = threadIdx.x;
    int i = tid >> 4, j = tid & 15;
    float dot = 0.f;
    #pragma unroll 4
    for (int k = 0; k < C; k++) dot = fmaf(kn[i*C + k], kn[j*C + k], dot);
    sym[i][j] = dot;
    __syncthreads();
    float nr = sqrtf(sym[i][i]) * sqrtf(sym[j][j]);
    float l = sym[i][j] / (nr + EPSF) - (i == j ? 1.f : 0.f);
    partial[tid] = l * l;
    __syncthreads();
    for (int s = 128; s > 0; s >>= 1) {
        if (tid < s) partial[tid] += partial[tid + s];
        __syncthreads();
    }
    if (tid == 0) {
        float loss = 0.1f * logf(partial[0] + 1.f);
        for (int idx = Bn*C*HW; idx < out_size; idx++) out[idx] = loss;
    }
}

// ---------------- out = x + Mhi@(x_hi+x_lo) + d via mma.sync tf32 (2-pass) ----------------
// Warps split PIXELS (n), share all 128 rows (m): 45% fewer LDS per MMA.
// grid (HW/128, Bn), block 256.
__global__ __launch_bounds__(256) void out_mma_kernel(const float* __restrict__ x,
                                                      float* __restrict__ out) {
    const int p0 = blockIdx.x * 128;
    const int b  = blockIdx.y;
    const int tid = threadIdx.x;
    const int w = tid >> 5, lane = tid & 31;
    const int gid = lane >> 2, tig = lane & 3;

    __shared__ uint32_t a_hi[C*20];       // [row][k] pitch 20 (M chunk, tf32 bits)
    __shared__ uint32_t xs_hi[16*136];    // [k][p]
    __shared__ uint32_t xs_lo[16*136];
    __shared__ float dsm[C];

    const uint32_t* Mb = reinterpret_cast<const uint32_t*>(g_M + b*C*C);
    const float* xb = x + (size_t)b*C*HW;

    if (tid < C) dsm[tid] = g_d[b*C + tid];

    // acc[mt][nt][4]: mt = m16 tile (8), nt = n8 tile within warp's 16-pixel strip (2)
    float acc[8][2][4];
    #pragma unroll
    for (int mt = 0; mt < 8; mt++)
        #pragma unroll
        for (int nt = 0; nt < 2; nt++) {
            acc[mt][nt][0]=0.f; acc[mt][nt][1]=0.f; acc[mt][nt][2]=0.f; acc[mt][nt][3]=0.f;
        }

    const int mc = tid >> 1, mseg = tid & 1;
    const int xk = tid >> 4, xsg = tid & 15;

    uint4 vm[2]; float4 vx[2];
    #pragma unroll
    for (int j = 0; j < 2; j++) {
        vm[j] = *reinterpret_cast<const uint4*>(Mb + mc*C + mseg*8 + j*4);
        vx[j] = *reinterpret_cast<const float4*>(xb + (size_t)xk*HW + p0 + xsg*8 + j*4);
    }

    for (int ch = 0; ch < 8; ch++) {
        __syncthreads();
        #pragma unroll
        for (int j = 0; j < 2; j++)
            *reinterpret_cast<uint4*>(&a_hi[mc*20 + mseg*8 + j*4]) = vm[j];
        #pragma unroll
        for (int j = 0; j < 2; j++) {
            uint4 h, l;
            h.x = f2tf32(vx[j].x); l.x = f2tf32(vx[j].x - __uint_as_float(h.x));
            h.y = f2tf32(vx[j].y); l.y = f2tf32(vx[j].y - __uint_as_float(h.y));
            h.z = f2tf32(vx[j].z); l.z = f2tf32(vx[j].z - __uint_as_float(h.z));
            h.w = f2tf32(vx[j].w); l.w = f2tf32(vx[j].w - __uint_as_float(h.w));
            *reinterpret_cast<uint4*>(&xs_hi[xk*136 + xsg*8 + j*4]) = h;
            *reinterpret_cast<uint4*>(&xs_lo[xk*136 + xsg*8 + j*4]) = l;
        }
        __syncthreads();
        // prefetch next chunk while MMAs run
        if (ch + 1 < 8) {
            const int k0n = (ch + 1)*16;
            #pragma unroll
            for (int j = 0; j < 2; j++) {
                vm[j] = *reinterpret_cast<const uint4*>(Mb + mc*C + k0n + mseg*8 + j*4);
                vx[j] = *reinterpret_cast<const float4*>(xb + (size_t)(k0n + xk)*HW + p0 + xsg*8 + j*4);
            }
        }
        #pragma unroll
        for (int k8 = 0; k8 < 2; k8++) {
            const int kc = k8*8 + tig;
            uint32_t Bf[2][4];
            #pragma unroll
            for (int nt = 0; nt < 2; nt++) {
                const int col = w*16 + nt*8 + gid;
                Bf[nt][0] = xs_hi[ kc   *136 + col];
                Bf[nt][1] = xs_hi[(kc+4)*136 + col];
                Bf[nt][2] = xs_lo[ kc   *136 + col];
                Bf[nt][3] = xs_lo[(kc+4)*136 + col];
            }
            #pragma unroll
            for (int mt = 0; mt < 8; mt++) {
                uint32_t a0 = a_hi[(mt*16 + gid    )*20 + kc];
                uint32_t a1 = a_hi[(mt*16 + gid + 8)*20 + kc];
                uint32_t a2 = a_hi[(mt*16 + gid    )*20 + kc + 4];
                uint32_t a3 = a_hi[(mt*16 + gid + 8)*20 + kc + 4];
                #pragma unroll
                for (int nt = 0; nt < 2; nt++) {
                    MMA_TF32(acc[mt][nt], a0, a1, a2, a3, Bf[nt][0], Bf[nt][1]);
                    MMA_TF32(acc[mt][nt], a0, a1, a2, a3, Bf[nt][2], Bf[nt][3]);
                }
            }
        }
    }

    // direct epilogue: out[r][p] = x[r][p] + delta + d[r]   (float2 per fragment row)
    float* ob = out + (size_t)b*C*HW;
    #pragma unroll
    for (int mt = 0; mt < 8; mt++) {
        const int r0 = mt*16 + gid, r1 = r0 + 8;
        const float d0 = dsm[r0], d1 = dsm[r1];
        #pragma unroll
        for (int nt = 0; nt < 2; nt++) {
            const int p = p0 + w*16 + nt*8 + 2*tig;
            float2 xv0 = *reinterpret_cast<const float2*>(xb + (size_t)r0*HW + p);
            float2 xv1 = *reinterpret_cast<const float2*>(xb + (size_t)r1*HW + p);
            float2 o0, o1;
            o0.x = xv0.x + acc[mt][nt][0] + d0;
            o0.y = xv0.y + acc[mt][nt][1] + d0;
            o1.x = xv1.x + acc[mt][nt][2] + d1;
            o1.y = xv1.y + acc[mt][nt][3] + d1;
            *reinterpret_cast<float2*>(ob + (size_t)r0*HW + p) = o0;
            *reinterpret_cast<float2*>(ob + (size_t)r1*HW + p) = o1;
        }
    }
}

extern "C" void kernel_launch(void* const* d_in, const int* in_sizes, int n_in,
                              void* d_out, int out_size) {
    const float* x     = (const float*)d_in[0];
    const float* Wsa   = (const float*)d_in[1];
    const float* bsa   = (const float*)d_in[2];
    const float* Wr    = (const float*)d_in[3];
    const float* br    = (const float*)d_in[4];
    const float* kn    = (const float*)d_in[5];
    const float* Wo    = (const float*)d_in[6];
    const float* bo    = (const float*)d_in[7];
    const float* alpha = (const float*)d_in[8];
    const float* sigma = (const float*)d_in[9];
    float* out = (float*)d_out;

    zero_kernel<<<(Bn*C*C + 255) / 256, 256>>>(Wsa);
    gram_mma_kernel<<<dim3(KS, Bn), 256>>>(x);
    hgemm_kernel<<<dim3(3, Bn), 256>>>(Wr, Wsa, Wo);
    reduce_kernel<<<dim3(Bn, 16), 128>>>(Wr, Wsa, Wo, kn);
    finalize_kernel<<<Bn, 128>>>(bsa, br, kn, Wo, bo, alpha, sigma);
    loss_kernel<<<1, 256>>>(kn, out, out_size);
    out_mma_kernel<<<dim3(HW/128, Bn), 256>>>(x, out);
}